// round 5
// baseline (speedup 1.0000x reference)
#include <cuda_runtime.h>
#include <cuda_bf16.h>
#include <float.h>
#include <math.h>

#define S 2048
#define D 1024
#define NMEM 32
#define PATCH 32

// ---------------- scratch (static device globals; no allocation) ----------------
__device__ float g_entropy [NMEM * S];            // per-memory row entropy
__device__ float g_entropy2[S];                   // query-scratch / aggregated row entropy
__device__ float g_part    [(NMEM + 2) * 32 * D]; // partial column sums (34 sources x 32 tiles)
__device__ float g_colmean [(NMEM + 1) * D];
__device__ unsigned long long g_cand[NMEM * 8 * 32]; // phase-1 top-k candidates
__device__ int   g_topidx  [NMEM * PATCH];
__device__ int   g_fidx    [PATCH];
__device__ float g_agg     [S * D];               // query + scattered patches (= aggregated*33)
__device__ float g_emb     [(NMEM + 1) * D];
__device__ double g_norm   [NMEM + 1];

// ---------------- cp.async helpers --------------------------------------------------
__device__ __forceinline__ void cp_async16(float* sdst, const float* gsrc)
{
    unsigned sa = (unsigned)__cvta_generic_to_shared(sdst);
    asm volatile("cp.async.cg.shared.global [%0], [%1], 16;" :: "r"(sa), "l"(gsrc) : "memory");
}
// issue one 4KB row: lane l copies 8 x 16B, then commit as one group
__device__ __forceinline__ void issue_row(const float* g, float* slot, int l)
{
#pragma unroll
    for (int j = 0; j < 8; j++)
        cp_async16(slot + (l + 32 * j) * 4, g + (l + 32 * j) * 4);
    asm volatile("cp.async.commit_group;" ::: "memory");
}

// ---------------- kernel A: row stats + partial colsums, 3-deep cp.async pipeline ---
// grid = n_count*32 blocks, 256 threads (8 warps). Warp w handles rows tile*64+w*8 .. +7.
// dynamic smem: ring[8 warps][3 slots][1024 floats] = 96KB (reused as cs[8][1024] at end)
__global__ void __launch_bounds__(256)
rowstats_kernel(const float* __restrict__ src_in, int esel, int part_base)
{
    extern __shared__ float sm[];
    const float* src = src_in ? src_in : g_agg;
    const int bx = blockIdx.x;
    const int tile = bx & 31;
    const int n    = bx >> 5;
    const int t = threadIdx.x;
    const int w = t >> 5, l = t & 31;

    const int row0 = tile * 64 + w * 8;
    const float* rowbase = src + (size_t)n * S * D + (size_t)row0 * D;
    float* ring = sm + w * 3072;

    // prime 3-deep
    issue_row(rowbase + 0 * (size_t)D, ring + 0 * 1024, l);
    issue_row(rowbase + 1 * (size_t)D, ring + 1 * 1024, l);
    issue_row(rowbase + 2 * (size_t)D, ring + 2 * 1024, l);

    float4 colacc[8];
#pragma unroll
    for (int j = 0; j < 8; j++) colacc[j] = make_float4(0.f, 0.f, 0.f, 0.f);
    float s1[8], s2[8];

#pragma unroll
    for (int k = 0; k < 8; k++) {
        if (k <= 5)      asm volatile("cp.async.wait_group 2;" ::: "memory");
        else if (k == 6) asm volatile("cp.async.wait_group 1;" ::: "memory");
        else             asm volatile("cp.async.wait_group 0;" ::: "memory");
        // data in this slot is strictly thread-private (same lane wrote it) -> no barrier
        const float4* rp = reinterpret_cast<const float4*>(ring + (k % 3) * 1024);
        float a = 0.f, b = 0.f;
#pragma unroll
        for (int j = 0; j < 8; j++) {
            float4 x = rp[l + 32 * j];
            colacc[j].x += x.x; colacc[j].y += x.y; colacc[j].z += x.z; colacc[j].w += x.w;
            a += (x.x + x.y) + (x.z + x.w);
            b += (x.x * x.x + x.y * x.y) + (x.z * x.z + x.w * x.w);
        }
        s1[k] = a; s2[k] = b;
        if (k < 5) issue_row(rowbase + (size_t)(k + 3) * D, ring + (k % 3) * 1024, l);
    }

    // batched float butterfly reduce: 80 independent shuffles, no serial per-row chains
#pragma unroll
    for (int off = 16; off; off >>= 1) {
#pragma unroll
        for (int k = 0; k < 8; k++) {
            s1[k] += __shfl_xor_sync(0xffffffffu, s1[k], off);
            s2[k] += __shfl_xor_sync(0xffffffffu, s2[k], off);
        }
    }
    // lane k (0..7) stores entropy for row row0+k
#pragma unroll
    for (int k = 0; k < 8; k++) {
        if (l == k) {
            double d1 = (double)s1[k], d2 = (double)s2[k];
            double var = (d2 - d1 * d1 * (1.0 / (double)D)) * (1.0 / (double)(D - 1));
            float e = var > 0.0 ? sqrtf((float)var) : 0.f;
            if (esel == 0) g_entropy[(size_t)n * S + row0 + k] = e;
            else           g_entropy2[row0 + k] = e;
        }
    }

    // reuse ring as cs[8][1024] for deterministic column-sum combine
    __syncthreads();            // everyone finished reading their ring slots
    float* cs = sm;
#pragma unroll
    for (int j = 0; j < 8; j++)
        reinterpret_cast<float4*>(&cs[w * 1024 + 4 * (l + 32 * j)])[0] = colacc[j];
    __syncthreads();
#pragma unroll
    for (int g = 0; g < 4; g++) {
        const int d = t + 256 * g;
        float ssum = 0.f;
#pragma unroll
        for (int w2 = 0; w2 < 8; w2++) ssum += cs[w2 * 1024 + d];
        g_part[(size_t)(part_base + bx) * D + d] = ssum;
    }
}

// ---------------- kernel B: reduce partial colsums -> colmean ----------------------
__global__ void colmean_kernel(int n0)
{
    const int n = n0 + blockIdx.x, t = threadIdx.x;
#pragma unroll
    for (int g = 0; g < 4; g++) {
        const int d = t + 256 * g;
        float s = 0.f;
#pragma unroll 8
        for (int p = 0; p < 32; p++) s += g_part[(size_t)(n * 32 + p) * D + d];
        g_colmean[n * D + d] = s * (1.0f / (float)S);
    }
}

// ---------------- topk phase 1: each 1-warp block -> top-32 of its 256 elems --------
// key = (float_bits << 32) | ~row  (u64 max == value desc, then lowest row)
__global__ void topk1_kernel(int esel)
{
    const int b = blockIdx.x, l = threadIdx.x;
    const float* e = (esel == 0 ? g_entropy : g_entropy2) + (size_t)b * 256;

    unsigned long long key[8];
#pragma unroll
    for (int j = 0; j < 8; j++) {
        const int loc = l + 32 * j;
        const int row = ((b & 7) * 256 + loc);                 // row within its 2048 source
        const unsigned v = __float_as_uint(e[loc]);            // entropy >= 0
        key[j] = ((unsigned long long)v << 32) | (unsigned)(~row);
    }

    for (int it = 0; it < 32; it++) {
        unsigned long long m = key[0];
#pragma unroll
        for (int j = 1; j < 8; j++) m = (key[j] > m) ? key[j] : m;
#pragma unroll
        for (int off = 16; off; off >>= 1) {
            unsigned long long o = __shfl_xor_sync(0xffffffffu, m, off);
            m = (o > m) ? o : m;
        }
        if (l == 0) g_cand[b * 32 + it] = m;
#pragma unroll
        for (int j = 0; j < 8; j++) if (key[j] == m) key[j] = 0ull;
    }
}

// ---------------- topk phase 2: exact rank among 256 candidates ---------------------
__global__ void topk2_kernel(int osel)
{
    __shared__ unsigned long long c[256];
    const int n = blockIdx.x, t = threadIdx.x;
    const unsigned long long k = g_cand[n * 256 + t];
    c[t] = k;
    __syncthreads();
    int r = 0;
#pragma unroll 8
    for (int i = 0; i < 256; i++) r += (c[i] > k) ? 1 : 0;
    if (r < PATCH) {
        const int row = (int)(~(unsigned)(k & 0xffffffffu));
        if (osel == 0) g_topidx[n * PATCH + r] = row;
        else           g_fidx[r] = row;
    }
}

// ---------------- kernel D: agg = query copy, out[0..S*D) = 0 -----------------------
__global__ void init_agg_kernel(const float* __restrict__ q, float* __restrict__ out)
{
    const int i = blockIdx.x * blockDim.x + threadIdx.x;  // float4 index
    float4 v = reinterpret_cast<const float4*>(q)[i];
    reinterpret_cast<float4*>(g_agg)[i] = v;
    reinterpret_cast<float4*>(out)[i] = make_float4(0.f, 0.f, 0.f, 0.f);
}

__device__ __forceinline__ float trunc_clip(float x)
{
    return truncf(fminf(fmaxf(x, -128.f), 127.f));
}

// ---------------- kernel E: scatter truncated patches into agg ----------------------
__global__ void scatter_kernel(const float* __restrict__ mem)
{
    const int b = blockIdx.x;
    const int n = b >> 5, j = b & 31;
    const int row = g_topidx[n * PATCH + j];
    const int t = threadIdx.x;
    float4 x = reinterpret_cast<const float4*>(mem + ((size_t)n * S + row) * D)[t];
    float* dst = g_agg + (size_t)row * D + 4 * t;
    atomicAdd(dst + 0, trunc_clip(x.x));
    atomicAdd(dst + 1, trunc_clip(x.y));
    atomicAdd(dst + 2, trunc_clip(x.z));
    atomicAdd(dst + 3, trunc_clip(x.w));
}

// ---------------- kernel H: write recon rows -----------------------------------------
__global__ void recon_kernel(float* __restrict__ out)
{
    const int row = g_fidx[blockIdx.x];
    const int t = threadIdx.x;
    float4 x = reinterpret_cast<float4*>(g_agg + (size_t)row * D)[t];
    const float inv = 1.0f / 33.0f;
    float4 r;
    r.x = trunc_clip(x.x * inv);
    r.y = trunc_clip(x.y * inv);
    r.z = trunc_clip(x.z * inv);
    r.w = trunc_clip(x.w * inv);
    reinterpret_cast<float4*>(out + (size_t)row * D)[t] = r;
}

// ---------------- kernel M: meta MLP (33 blocks x 128 threads) -----------------------
__global__ void mlp_kernel(const float* __restrict__ surprise,
                           const float* __restrict__ W1, const float* __restrict__ b1,
                           const float* __restrict__ W2, const float* __restrict__ b2)
{
    const int n = blockIdx.x;       // 0..31 memories, 32 = query
    const int t = threadIdx.x;      // 128
    __shared__ float feat[1028];
    __shared__ float hsm[128];
    __shared__ double red[128];

#pragma unroll
    for (int g = 0; g < 8; g++) feat[t + 128 * g] = g_colmean[n * D + t + 128 * g];
    if (t == 0) {
        feat[1024] = (n < NMEM) ? surprise[n] : 0.f;
        feat[1025] = 0.f; feat[1026] = 0.f;
    }
    __syncthreads();

    float a0 = b1[t], a1 = 0.f, a2 = 0.f, a3 = 0.f;
    for (int i = 0; i < 1024; i += 4) {
        a0 = fmaf(feat[i + 0], W1[(i + 0) * 128 + t], a0);
        a1 = fmaf(feat[i + 1], W1[(i + 1) * 128 + t], a1);
        a2 = fmaf(feat[i + 2], W1[(i + 2) * 128 + t], a2);
        a3 = fmaf(feat[i + 3], W1[(i + 3) * 128 + t], a3);
    }
    for (int i = 1024; i < 1027; i++) a0 = fmaf(feat[i], W1[i * 128 + t], a0);
    float acc = (a0 + a1) + (a2 + a3);
    hsm[t] = acc > 0.f ? acc : 0.f;
    __syncthreads();

    double nrm = 0.0;
#pragma unroll
    for (int g = 0; g < 8; g++) {
        const int d = t + 128 * g;
        float e0 = b2[d], e1 = 0.f, e2 = 0.f, e3 = 0.f;
#pragma unroll
        for (int k = 0; k < 128; k += 4) {
            e0 = fmaf(hsm[k + 0], W2[(k + 0) * D + d], e0);
            e1 = fmaf(hsm[k + 1], W2[(k + 1) * D + d], e1);
            e2 = fmaf(hsm[k + 2], W2[(k + 2) * D + d], e2);
            e3 = fmaf(hsm[k + 3], W2[(k + 3) * D + d], e3);
        }
        float e = (e0 + e1) + (e2 + e3);
        g_emb[n * D + d] = e;
        nrm += (double)e * (double)e;
    }
    red[t] = nrm;
    __syncthreads();
#pragma unroll
    for (int off = 64; off; off >>= 1) { if (t < off) red[t] += red[t + off]; __syncthreads(); }
    if (t == 0) g_norm[n] = sqrt(red[0]);
}

// ---------------- kernel S: sims + rank-ordered top_idx (1 block, warp per memory) --
__global__ void __launch_bounds__(1024) sims_kernel(const float* __restrict__ pm,
                                                    float* __restrict__ out)
{
    const int t = threadIdx.x, w = t >> 5, l = t & 31;   // w = memory index
    const float* en = g_emb + (size_t)w * D;
    const float* eq = g_emb + (size_t)NMEM * D;
    const int base = l * 32;
    double a0 = 0.0, a1 = 0.0, a2 = 0.0, a3 = 0.0;
#pragma unroll
    for (int j = 0; j < 32; j += 4) {
        a0 += (double)en[base + j + 0] * (double)eq[base + j + 0];
        a1 += (double)en[base + j + 1] * (double)eq[base + j + 1];
        a2 += (double)en[base + j + 2] * (double)eq[base + j + 2];
        a3 += (double)en[base + j + 3] * (double)eq[base + j + 3];
    }
    double p = (a0 + a1) + (a2 + a3);
#pragma unroll
    for (int off = 16; off; off >>= 1) p += __shfl_xor_sync(0xffffffffu, p, off);

    __shared__ float ssim[NMEM];
    if (l == 0) {
        double sim = p / (fmax(g_norm[w], 1e-8) * fmax(g_norm[NMEM], 1e-8)) * (double)pm[w];
        out[(size_t)S * D + w] = (float)sim;
        ssim[w] = (float)sim;
    }
    __syncthreads();
    if (w == 0) {
        const float v = ssim[l];
        int r = 0;
#pragma unroll
        for (int i = 0; i < NMEM; i++) {
            const float vi = ssim[i];
            r += ((vi > v) || (vi == v && i < l)) ? 1 : 0;
        }
        out[(size_t)S * D + NMEM + r] = (float)l;
    }
}

// ---------------- launch ------------------------------------------------------------
extern "C" void kernel_launch(void* const* d_in, const int* in_sizes, int n_in,
                              void* d_out, int out_size)
{
    const float* query    = (const float*)d_in[0];
    const float* memories = (const float*)d_in[1];
    const float* surprise = (const float*)d_in[2];
    const float* pm       = (const float*)d_in[3];
    const float* W1       = (const float*)d_in[4];
    const float* b1       = (const float*)d_in[5];
    const float* W2       = (const float*)d_in[6];
    const float* b2       = (const float*)d_in[7];
    float* out = (float*)d_out;

    const int RS_SMEM = 96 * 1024;
    static int attr_done = 0;
    if (!attr_done) {
        cudaFuncSetAttribute(rowstats_kernel,
                             cudaFuncAttributeMaxDynamicSharedMemorySize, RS_SMEM);
        attr_done = 1;
    }

    // 1) agg = query, zero recon region of out
    init_agg_kernel<<<(S * D / 4) / 256, 256>>>(query, out);
    // 2) query column sums (entropy side -> g_entropy2 scratch, overwritten later)
    rowstats_kernel<<<32, 256, RS_SMEM>>>(query, 1, NMEM * 32);
    // 3) query colmean (source slot 32)
    colmean_kernel<<<1, 256>>>(NMEM);
    // 4) per-memory row entropy + partial colsums (268MB pass)  <- profiled slot
    rowstats_kernel<<<NMEM * 32, 256, RS_SMEM>>>(memories, 0, 0);
    // 5-6) per-memory top-32 entropy rows
    topk1_kernel<<<NMEM * 8, 32>>>(0);
    topk2_kernel<<<NMEM, 256>>>(0);
    // 7) scatter truncated patches (exact integer fp adds)
    scatter_kernel<<<NMEM * PATCH, 256>>>(memories);
    // 8) row entropy of aggregated
    rowstats_kernel<<<32, 256, RS_SMEM>>>(nullptr, 1, (NMEM + 1) * 32);
    // 9-10) final top-32 rows
    topk1_kernel<<<8, 32>>>(1);
    topk2_kernel<<<1, 256>>>(1);
    // 11) recon rows (trunc(clip(agg/33)))
    recon_kernel<<<PATCH, 256>>>(out);
    // 12) memory colmeans
    colmean_kernel<<<NMEM, 256>>>(0);
    // 13) meta-learner embeddings + norms
    mlp_kernel<<<NMEM + 1, 128>>>(surprise, W1, b1, W2, b2);
    // 14) sims + top_idx
    sims_kernel<<<1, 1024>>>(pm, out);
}